// round 1
// baseline (speedup 1.0000x reference)
#include <cuda_runtime.h>
#include <math.h>

#define BATCH  512
#define TSTEPS 55
#define CDIM   512
#define DDIM   512
#define KDIM   64
#define NL     3
#define G4D    2048      // 4*D gate width
#define HW     1536      // L*D concat width of h storage

// ---------------- scratch (static device allocations; no cudaMalloc) ----------
__device__ float g_pregate[(size_t)NL * TSTEPS * BATCH * G4D]; // x@wx + biases, accumulated with recurrent terms
__device__ float g_prer[(size_t)NL * TSTEPS * BATCH * KDIM];   // x@wr
__device__ float g_hall[(size_t)(TSTEPS + 1) * BATCH * HW];    // slab 0 = zeros (t=-1), slab t+1 = h at step t
__device__ float g_c[(size_t)NL * BATCH * DDIM];               // cell states
__device__ float g_d[(size_t)NL * BATCH * KDIM];               // decayed keys

// ---------------- init: zero state, seed keys (re-run each launch => deterministic)
__global__ void init_kernel(const float* __restrict__ init_keys) {
    int i = blockIdx.x * blockDim.x + threadIdx.x;
    if (i < BATCH * HW)        g_hall[i] = 0.0f;
    if (i < NL * BATCH * DDIM) g_c[i]   = 0.0f;
    if (i < NL * BATCH * KDIM) g_d[i]   = init_keys[i % (BATCH * KDIM)];
}

// ---------------- generic fp32 GEMM: C(+)= sum_s A_s @ W_s  ----------------
// A_s: [M, segK] rows with stride lda (segmented concat along K)
// W_s: [segK, N] row-major, stride ldb
// mode 0: C[m*ldc+n] += acc                      (recurrent gate accumulate)
// mode 1: C[((m%p1)*p2 + m/p1)*ldc + n] = acc + bias1[n] + bias2[n]   (assign w/ row permute)
#define BM  64
#define BN  128
#define BKT 16

__global__ __launch_bounds__(256)
void gemm_kernel(const float* __restrict__ A0, const float* __restrict__ A1,
                 const float* __restrict__ A2,
                 const float* __restrict__ W0, const float* __restrict__ W1,
                 const float* __restrict__ W2,
                 int nseg, int segK, int lda, int ldb,
                 float* __restrict__ C, int ldc, int N,
                 const float* __restrict__ bias1, const float* __restrict__ bias2,
                 int mode, int p1, int p2)
{
    __shared__ float As[BKT][BM + 4];
    __shared__ float Bs[BKT][BN + 4];
    int tid = threadIdx.x;
    int bm = blockIdx.y * BM;
    int bn = blockIdx.x * BN;
    int a_m = tid >> 2, a_k = (tid & 3) * 4;   // A tile: 64m x 16k, float4 along k
    int b_k = tid >> 5, b_n = (tid & 31) * 4;  // B tile: 16k x 128n, float4 along n
    int ty = tid >> 4, tx = tid & 15;          // micro-tile: rows ty*4.., cols tx*8..

    float acc[4][8];
#pragma unroll
    for (int i = 0; i < 4; i++)
#pragma unroll
        for (int j = 0; j < 8; j++) acc[i][j] = 0.0f;

    for (int s = 0; s < nseg; s++) {
        const float* A = (s == 0) ? A0 : ((s == 1) ? A1 : A2);
        const float* W = (s == 0) ? W0 : ((s == 1) ? W1 : W2);
        for (int k0 = 0; k0 < segK; k0 += BKT) {
            float4 av = *(const float4*)(A + (size_t)(bm + a_m) * lda + k0 + a_k);
            float4 bv0, bv1;
            int n = bn + b_n;
            if (n < N) {
                bv0 = *(const float4*)(W + (size_t)(k0 + b_k) * ldb + n);
                bv1 = *(const float4*)(W + (size_t)(k0 + b_k + 8) * ldb + n);
            } else {
                bv0 = make_float4(0.f, 0.f, 0.f, 0.f);
                bv1 = bv0;
            }
            __syncthreads();
            As[a_k + 0][a_m] = av.x;
            As[a_k + 1][a_m] = av.y;
            As[a_k + 2][a_m] = av.z;
            As[a_k + 3][a_m] = av.w;
            *(float4*)&Bs[b_k][b_n]     = bv0;
            *(float4*)&Bs[b_k + 8][b_n] = bv1;
            __syncthreads();
#pragma unroll
            for (int kk = 0; kk < BKT; kk++) {
                float4 a  = *(const float4*)&As[kk][ty * 4];
                float4 b0 = *(const float4*)&Bs[kk][tx * 8];
                float4 b1 = *(const float4*)&Bs[kk][tx * 8 + 4];
                float av4[4] = {a.x, a.y, a.z, a.w};
                float bv8[8] = {b0.x, b0.y, b0.z, b0.w, b1.x, b1.y, b1.z, b1.w};
#pragma unroll
                for (int i = 0; i < 4; i++)
#pragma unroll
                    for (int j = 0; j < 8; j++)
                        acc[i][j] += av4[i] * bv8[j];
            }
        }
    }

    if (mode == 0) {
#pragma unroll
        for (int i = 0; i < 4; i++) {
            int row = bm + ty * 4 + i;
            float* Cr = C + (size_t)row * ldc;
#pragma unroll
            for (int j = 0; j < 8; j++) {
                int col = bn + tx * 8 + j;
                if (col < N) Cr[col] += acc[i][j];
            }
        }
    } else {
#pragma unroll
        for (int i = 0; i < 4; i++) {
            int m = bm + ty * 4 + i;
            size_t crow = (size_t)(m % p1) * p2 + (size_t)(m / p1);
            float* Cr = C + crow * ldc;
#pragma unroll
            for (int j = 0; j < 8; j++) {
                int col = bn + tx * 8 + j;
                if (col < N) {
                    float v = acc[i][j];
                    if (bias1) v += bias1[col];
                    if (bias2) v += bias2[col];
                    Cr[col] = v;
                }
            }
        }
    }
}

// ---------------- K1: gr -> r -> d update (per layer, per step) ----------------
// gr[b,k] = prer[b,k] + sum_{j<l} hnew_j . wr_l[C+j*D + :, k] + (1/3) * hprev_j . wl_j[:, k]
// d[b,k] *= sigmoid(gr)
__global__ __launch_bounds__(256)
void k1_kernel(int l, const float* __restrict__ prer,
               const float* __restrict__ hall_cur, const float* __restrict__ hall_prev,
               const float* __restrict__ wr,
               const float* __restrict__ wl0, const float* __restrict__ wl1,
               float* __restrict__ dstate)
{
    __shared__ float hs[4][512];
    int tx = threadIdx.x;          // k index 0..63
    int ty = threadIdx.y;          // local batch 0..3
    int tid = ty * 64 + tx;
    int b = blockIdx.x * 4 + ty;
    float acc = prer[b * KDIM + tx];
    for (int j = 0; j < l; j++) {
        __syncthreads();
        for (int i = tid; i < 4 * 512; i += 256) {
            int rb = i >> 9, c = i & 511;
            hs[rb][c] = hall_cur[(size_t)(blockIdx.x * 4 + rb) * HW + j * DDIM + c];
        }
        __syncthreads();
        {
            const float* W = wr + (size_t)(CDIM + j * DDIM) * KDIM;
            float s0 = 0.f, s1 = 0.f, s2 = 0.f, s3 = 0.f;
            for (int c = 0; c < 512; c += 4) {
                s0 += hs[ty][c]     * W[(size_t)c * KDIM + tx];
                s1 += hs[ty][c + 1] * W[(size_t)(c + 1) * KDIM + tx];
                s2 += hs[ty][c + 2] * W[(size_t)(c + 2) * KDIM + tx];
                s3 += hs[ty][c + 3] * W[(size_t)(c + 3) * KDIM + tx];
            }
            acc += (s0 + s1) + (s2 + s3);
        }
        __syncthreads();
        for (int i = tid; i < 4 * 512; i += 256) {
            int rb = i >> 9, c = i & 511;
            hs[rb][c] = hall_prev[(size_t)(blockIdx.x * 4 + rb) * HW + j * DDIM + c];
        }
        __syncthreads();
        {
            const float* Wl = (j == 0) ? wl0 : wl1;
            float s0 = 0.f, s1 = 0.f, s2 = 0.f, s3 = 0.f;
            for (int c = 0; c < 512; c += 4) {
                s0 += hs[ty][c]     * Wl[(size_t)c * KDIM + tx];
                s1 += hs[ty][c + 1] * Wl[(size_t)(c + 1) * KDIM + tx];
                s2 += hs[ty][c + 2] * Wl[(size_t)(c + 2) * KDIM + tx];
                s3 += hs[ty][c + 3] * Wl[(size_t)(c + 3) * KDIM + tx];
            }
            acc += (1.0f / 3.0f) * ((s0 + s1) + (s2 + s3));
        }
    }
    float r = 1.0f / (1.0f + expf(-acc));
    dstate[b * KDIM + tx] *= r;
}

// ---------------- K2: gate nonlinearity + tanh(d @ wd) + c/h update ------------
__global__ __launch_bounds__(512)
void k2_kernel(const float* __restrict__ gate, const float* __restrict__ dvals,
               const float* __restrict__ wd, float* __restrict__ cst,
               float* __restrict__ hout)
{
    int b = blockIdx.x, dd = threadIdx.x;
    __shared__ float ds[KDIM];
    if (dd < KDIM) ds[dd] = dvals[b * KDIM + dd];
    __syncthreads();
    float s0 = 0.f, s1 = 0.f, s2 = 0.f, s3 = 0.f;
#pragma unroll
    for (int k = 0; k < KDIM; k += 4) {
        s0 += ds[k]     * wd[(size_t)k * DDIM + dd];
        s1 += ds[k + 1] * wd[(size_t)(k + 1) * DDIM + dd];
        s2 += ds[k + 2] * wd[(size_t)(k + 2) * DDIM + dd];
        s3 += ds[k + 3] * wd[(size_t)(k + 3) * DDIM + dd];
    }
    float dwd = tanhf((s0 + s1) + (s2 + s3));
    const float* g = gate + (size_t)b * G4D;
    float f  = 1.0f / (1.0f + expf(-g[dd]));
    float ii = 1.0f / (1.0f + expf(-g[DDIM + dd]));
    float o  = 1.0f / (1.0f + expf(-g[2 * DDIM + dd]));
    float cb = tanhf(g[3 * DDIM + dd]);
    float c = f * cst[(size_t)b * DDIM + dd] + ii * cb + dwd;
    cst[(size_t)b * DDIM + dd] = c;
    hout[(size_t)b * HW + dd] = o * tanhf(c);
}

// ---------------- host orchestration (graph-capturable: launches only) ---------
extern "C" void kernel_launch(void* const* d_in, const int* in_sizes, int n_in,
                              void* d_out, int out_size)
{
    (void)n_in; (void)out_size;
    const float* inputs    = (const float*)d_in[0];
    const float* init_keys = (const float*)d_in[1];
    const float *wx[NL], *wxb[NL], *wh[NL], *whb[NL], *wr[NL], *wl[NL];

    // Runtime input-order detection:
    // dict order:  idx4 = wh0_w (512*2048 = 1048576)
    // sig  order:  idx4 = wx1_w (1024*2048 = 2097152)
    bool dict_order = (in_sizes[4] == 1048576);
    if (dict_order) {
        for (int l = 0; l < NL; l++) {
            int b0 = 2 + l * 6;
            wx[l]  = (const float*)d_in[b0];
            wxb[l] = (const float*)d_in[b0 + 1];
            wh[l]  = (const float*)d_in[b0 + 2];
            whb[l] = (const float*)d_in[b0 + 3];
            wr[l]  = (const float*)d_in[b0 + 4];
            wl[l]  = (const float*)d_in[b0 + 5];
        }
    } else {
        for (int l = 0; l < NL; l++) {
            wx[l]  = (const float*)d_in[2 + 2 * l];
            wxb[l] = (const float*)d_in[3 + 2 * l];
            wh[l]  = (const float*)d_in[8 + 2 * l];
            whb[l] = (const float*)d_in[9 + 2 * l];
            wr[l]  = (const float*)d_in[14 + l];
            wl[l]  = (const float*)d_in[17 + l];
        }
    }
    const float* wd    = (const float*)d_in[20];
    const float* projw = (const float*)d_in[21];
    const float* projb = (const float*)d_in[22];
    float* out = (float*)d_out;

    float *pregate, *prer, *hall, *cst, *dst;
    cudaGetSymbolAddress((void**)&pregate, g_pregate);
    cudaGetSymbolAddress((void**)&prer,    g_prer);
    cudaGetSymbolAddress((void**)&hall,    g_hall);
    cudaGetSymbolAddress((void**)&cst,     g_c);
    cudaGetSymbolAddress((void**)&dst,     g_d);

    init_kernel<<<(BATCH * HW + 255) / 256, 256>>>(init_keys);

    // ---- time-parallel precompute of x projections (rows m = b*T + t) ----
    const int MBT = BATCH * TSTEPS;   // 28160
    for (int l = 0; l < NL; l++) {
        gemm_kernel<<<dim3(G4D / BN, MBT / BM), 256>>>(
            inputs, nullptr, nullptr, wx[l], nullptr, nullptr,
            1, CDIM, CDIM, G4D,
            pregate + (size_t)l * TSTEPS * BATCH * G4D, G4D, G4D,
            wxb[l], whb[l], 1, TSTEPS, BATCH);
        gemm_kernel<<<dim3(1, MBT / BM), 256>>>(
            inputs, nullptr, nullptr, wr[l], nullptr, nullptr,
            1, CDIM, CDIM, KDIM,
            prer + (size_t)l * TSTEPS * BATCH * KDIM, KDIM, KDIM,
            nullptr, nullptr, 1, TSTEPS, BATCH);
    }

    // ---- sequential recurrence ----
    for (int t = 0; t < TSTEPS; t++) {
        float* hall_cur  = hall + (size_t)(t + 1) * BATCH * HW;
        float* hall_prev = hall + (size_t)t * BATCH * HW;
        for (int l = 0; l < NL; l++) {
            const float* Aseg[3] = {nullptr, nullptr, nullptr};
            const float* Wseg[3] = {nullptr, nullptr, nullptr};
            int ns = 0;
            for (int j = 0; j < l; j++) {           // current-step h of earlier layers
                Aseg[ns] = hall_cur + j * DDIM;
                Wseg[ns] = wx[l] + (size_t)(CDIM + j * DDIM) * G4D;
                ns++;
            }
            if (t > 0) {                             // previous-step h of this layer
                Aseg[ns] = hall_prev + l * DDIM;
                Wseg[ns] = wh[l];
                ns++;
            }
            float* gate = pregate + ((size_t)l * TSTEPS + t) * BATCH * G4D;
            if (ns > 0) {
                gemm_kernel<<<dim3(G4D / BN, BATCH / BM), 256>>>(
                    Aseg[0], Aseg[1], Aseg[2], Wseg[0], Wseg[1], Wseg[2],
                    ns, DDIM, HW, G4D,
                    gate, G4D, G4D, nullptr, nullptr, 0, 0, 0);
            }
            k1_kernel<<<BATCH / 4, dim3(64, 4)>>>(
                l, prer + ((size_t)l * TSTEPS + t) * BATCH * KDIM,
                hall_cur, hall_prev, wr[l], wl[0], wl[1],
                dst + (size_t)l * BATCH * KDIM);
            k2_kernel<<<BATCH, DDIM>>>(
                gate, dst + (size_t)l * BATCH * KDIM, wd,
                cst + (size_t)l * BATCH * DDIM, hall_cur + l * DDIM);
        }
    }

    // ---- deferred projection: rows m = t*B + b; out[b][t][n] ----
    gemm_kernel<<<dim3(512 / BN, MBT / BM), 256>>>(
        hall + (size_t)BATCH * HW, nullptr, nullptr, projw, nullptr, nullptr,
        1, HW, HW, 512,
        out, 512, 512, projb, nullptr, 1, BATCH, TSTEPS);
}